// round 7
// baseline (speedup 1.0000x reference)
#include <cuda_runtime.h>
#include <cuda_bf16.h>
#include <cstdint>

// ============================================================================
// SimplifiedTopologyExtractor — algebraic reduction:
//   out = ReLU(LayerNorm(emb[:, :, :256] @ W_enc + b_enc))
// (pooled == embeddings exactly; proj/cdist/topk is dead code.)
//
// fp32 GEMM via bf16 hi/lo split on mma.sync m16n8k16:
//   a*b ≈ ah*bh + ah*bl + al*bh   (err ~2^-18 rel).
// Round 7: (a) 3-stage cp.async pipeline, wait_group 1, loads 2 chunks ahead
// (R6 exposed L2 latency each chunk); (b) MTILE=64 with 512 threads (warp
// tile m16n128) — halves B L2 traffic to 128MB while keeping 16 warps/SM
// and acc=64 f32/thread (regs ~128, no spill).
// ============================================================================

#define THREADS 512
#define MTILE 64
#define KD 256
#define KCH 16
#define NCHUNK (KD / KCH)
#define STAGES 3

// smem strides/offsets (bytes)
#define A_STRIDE 48
#define B_STRIDE 1040
#define OFF_AH 0
#define OFF_AL (64 * A_STRIDE)                  // 3072
#define OFF_BH (2 * 64 * A_STRIDE)              // 6144
#define OFF_BL (OFF_BH + KCH * B_STRIDE)        // 22784
#define STAGE_B (OFF_BL + KCH * B_STRIDE)       // 39424 per stage
#define OFF_PS (STAGES * STAGE_B)               // 118272 : [64 rows][4 nw]
#define OFF_PQ (OFF_PS + 1024)
#define OFF_MZ (OFF_PQ + 1024)
#define SMEM_TOTAL (OFF_MZ + 512)               // 120832 (1 CTA/SM)

// prepped B (bf16 hi/lo), chunk-shaped: [chunk 16][part 2][kr 16][n 512]
__device__ __align__(16) unsigned char g_Bpre[16 * 32768];   // 512 KB

__device__ __forceinline__ uint32_t smem_u32(const void* p) {
    uint32_t a;
    asm("{ .reg .u64 t; cvta.to.shared.u64 t, %1; cvt.u32.u64 %0, t; }"
        : "=r"(a) : "l"(p));
    return a;
}

__device__ __forceinline__ void cp_async16(uint32_t dst, const void* src) {
    asm volatile("cp.async.cg.shared.global [%0], [%1], 16;\n"
                 :: "r"(dst), "l"(src));
}

__device__ __forceinline__ void ldsm4(uint32_t* r, uint32_t addr) {
    asm volatile("ldmatrix.sync.aligned.m8n8.x4.shared.b16 {%0,%1,%2,%3}, [%4];"
                 : "=r"(r[0]), "=r"(r[1]), "=r"(r[2]), "=r"(r[3]) : "r"(addr));
}
__device__ __forceinline__ void ldsm4t(uint32_t* r, uint32_t addr) {
    asm volatile("ldmatrix.sync.aligned.m8n8.x4.trans.shared.b16 {%0,%1,%2,%3}, [%4];"
                 : "=r"(r[0]), "=r"(r[1]), "=r"(r[2]), "=r"(r[3]) : "r"(addr));
}

__device__ __forceinline__ void mma16816(float* d, const uint32_t* a,
                                         uint32_t b0, uint32_t b1) {
    asm volatile(
        "mma.sync.aligned.m16n8k16.row.col.f32.bf16.bf16.f32 "
        "{%0,%1,%2,%3}, {%4,%5,%6,%7}, {%8,%9}, {%0,%1,%2,%3};"
        : "+f"(d[0]), "+f"(d[1]), "+f"(d[2]), "+f"(d[3])
        : "r"(a[0]), "r"(a[1]), "r"(a[2]), "r"(a[3]), "r"(b0), "r"(b1));
}

__device__ __forceinline__ void split_f4(float4 v, uint32_t& h01, uint32_t& h23,
                                         uint32_t& l01, uint32_t& l23) {
    float f[4] = {v.x, v.y, v.z, v.w};
    unsigned short hs[4], ls[4];
#pragma unroll
    for (int i = 0; i < 4; i++) {
        __nv_bfloat16 h = __float2bfloat16(f[i]);
        float rem = f[i] - __bfloat162float(h);
        __nv_bfloat16 l = __float2bfloat16(rem);
        hs[i] = __bfloat16_as_ushort(h);
        ls[i] = __bfloat16_as_ushort(l);
    }
    h01 = (uint32_t)hs[0] | ((uint32_t)hs[1] << 16);
    h23 = (uint32_t)hs[2] | ((uint32_t)hs[3] << 16);
    l01 = (uint32_t)ls[0] | ((uint32_t)ls[1] << 16);
    l23 = (uint32_t)ls[2] | ((uint32_t)ls[3] << 16);
}

// ---- prep B: W_enc[256,512] -> hi/lo bf16, chunk-tiled (1 MB traffic) ----
__global__ void prep_b_kernel(const float* __restrict__ W) {
    int t = blockIdx.x * 256 + threadIdx.x;   // 256 * 128
    int k  = t >> 7;
    int nq = t & 127;
    float4 v = *(const float4*)(W + (size_t)k * 512 + nq * 4);
    uint32_t h01, h23, l01, l23;
    split_f4(v, h01, h23, l01, l23);
    int c = k >> 4, kr = k & 15;
    size_t base = (size_t)c * 32768 + (size_t)kr * 1024 + nq * 8;
    *(uint2*)(g_Bpre + base)         = make_uint2(h01, h23);
    *(uint2*)(g_Bpre + base + 16384) = make_uint2(l01, l23);
}

// ---- GEMM + fused bias/LayerNorm/ReLU ----
__global__ void __launch_bounds__(THREADS, 1)
gemm_ln_kernel(const float* __restrict__ emb,
               const float* __restrict__ bias,
               const float* __restrict__ gamma,
               const float* __restrict__ beta,
               float* __restrict__ out)
{
    extern __shared__ __align__(1024) unsigned char smem[];
    const uint32_t sb = smem_u32(smem);
    const int tid = threadIdx.x;
    const int wid = tid >> 5;
    const int lane = tid & 31;
    const int mw = wid >> 2;       // 4 m-warps (rows mw*16..+16)
    const int nw = wid & 3;        // 4 n-warps (cols nw*128..+128)
    const int m0 = blockIdx.x * MTILE;

    float acc[16][4];
#pragma unroll
    for (int nt = 0; nt < 16; nt++)
#pragma unroll
        for (int e = 0; e < 4; e++) acc[nt][e] = 0.0f;

    // A staging: thread owns one float2 of the 64x16 chunk
    const int a_row = tid >> 3, a_kp = tid & 7;
    const float* a_src = emb + (size_t)(m0 + a_row) * 512 + a_kp * 2;
    const uint32_t a_off = (uint32_t)a_row * A_STRIDE + (uint32_t)a_kp * 4;

    // B staging: 4 x 16B per thread (32 KB / 512 threads)
    uint32_t b_dst_off[4];
#pragma unroll
    for (int i = 0; i < 4; i++) {
        int g = tid + i * 512;
        int part = g >> 10, kr = (g >> 6) & 15, col = g & 63;
        b_dst_off[i] = (uint32_t)(part ? OFF_BL : OFF_BH)
                     + (uint32_t)kr * B_STRIDE + (uint32_t)col * 16;
    }

#define ISSUE_B(cc) do {                                                        \
    const int _c = (cc);                                                        \
    const uint32_t _st = sb + (uint32_t)(_c % STAGES) * STAGE_B;                \
    _Pragma("unroll")                                                           \
    for (int _i = 0; _i < 4; _i++)                                              \
        cp_async16(_st + b_dst_off[_i],                                         \
                   g_Bpre + (size_t)_c * 32768 + (size_t)(tid + _i * 512) * 16);\
    asm volatile("cp.async.commit_group;");                                     \
} while (0)

#define STS_A(stg, v) do {                                                      \
    const uint32_t _so = (uint32_t)(stg) * STAGE_B;                             \
    __nv_bfloat16 _h0 = __float2bfloat16((v).x);                                \
    __nv_bfloat16 _h1 = __float2bfloat16((v).y);                                \
    __nv_bfloat16 _l0 = __float2bfloat16((v).x - __bfloat162float(_h0));        \
    __nv_bfloat16 _l1 = __float2bfloat16((v).y - __bfloat162float(_h1));        \
    uint32_t _h01 = (uint32_t)__bfloat16_as_ushort(_h0)                         \
                  | ((uint32_t)__bfloat16_as_ushort(_h1) << 16);                \
    uint32_t _l01 = (uint32_t)__bfloat16_as_ushort(_l0)                         \
                  | ((uint32_t)__bfloat16_as_ushort(_l1) << 16);                \
    *(uint32_t*)(smem + _so + OFF_AH + a_off) = _h01;                           \
    *(uint32_t*)(smem + _so + OFF_AL + a_off) = _l01;                           \
} while (0)

    // ---- prologue: stages 0,1 staged; A(2) prefetched to regs ----
    {
        float2 a0 = *(const float2*)(a_src);
        float2 a1 = *(const float2*)(a_src + 16);
        STS_A(0, a0);
        STS_A(1, a1);
    }
    ISSUE_B(0);
    ISSUE_B(1);
    float2 aR = *(const float2*)(a_src + 32);

    // ldmatrix lane addressing
    const uint32_t lrow = lane & 15, lchk = lane >> 4;
    const uint32_t aLane = lrow * A_STRIDE + lchk * 16
                         + (uint32_t)mw * 16 * A_STRIDE;
    const uint32_t bLane = lrow * B_STRIDE + lchk * 16 + (uint32_t)nw * 256;

#pragma unroll 1
    for (int c = 0; c < NCHUNK; ++c) {
        if (c < NCHUNK - 1)
            asm volatile("cp.async.wait_group 1;");
        else
            asm volatile("cp.async.wait_group 0;");
        __syncthreads();   // stage c ready for all; stage (c+2)%3's readers done

        if (c + 2 < NCHUNK) {
            STS_A((c + 2) % STAGES, aR);
            ISSUE_B(c + 2);
        }
        if (c + 3 < NCHUNK) aR = *(const float2*)(a_src + (c + 3) * 16);

        const uint32_t st = sb + (uint32_t)(c % STAGES) * STAGE_B;
        uint32_t Ah[4], Al[4];
        ldsm4(Ah, st + OFF_AH + aLane);
        ldsm4(Al, st + OFF_AL + aLane);
#pragma unroll
        for (int j = 0; j < 8; j++) {
            uint32_t Bh[4], Bl[4];
            ldsm4t(Bh, st + OFF_BH + (uint32_t)j * 32 + bLane);
            ldsm4t(Bl, st + OFF_BL + (uint32_t)j * 32 + bLane);
#pragma unroll
            for (int nn = 0; nn < 2; nn++) {
                float* d = acc[j * 2 + nn];
                mma16816(d, Ah, Bh[nn * 2], Bh[nn * 2 + 1]);
                mma16816(d, Ah, Bl[nn * 2], Bl[nn * 2 + 1]);
                mma16816(d, Al, Bh[nn * 2], Bh[nn * 2 + 1]);
            }
        }
    }

    // ======== fused epilogue: +bias, LayerNorm(512), *gamma+beta, ReLU ========
    const int g = lane >> 2, t4 = lane & 3;
    float* ps = (float*)(smem + OFF_PS);      // [64 rows][4 nw]
    float* pq = (float*)(smem + OFF_PQ);
    float2* mz = (float2*)(smem + OFF_MZ);    // [64] {mu, rstd}

    float s[2] = {0.f, 0.f}, q[2] = {0.f, 0.f};   // two rows: g, g+8
#pragma unroll
    for (int nt = 0; nt < 16; nt++) {
        const int col = nw * 128 + nt * 8 + t4 * 2;
        const float2 bv = *(const float2*)(bias + col);
        acc[nt][0] += bv.x; acc[nt][1] += bv.y;
        acc[nt][2] += bv.x; acc[nt][3] += bv.y;
        s[0] += acc[nt][0] + acc[nt][1];
        q[0] += acc[nt][0] * acc[nt][0] + acc[nt][1] * acc[nt][1];
        s[1] += acc[nt][2] + acc[nt][3];
        q[1] += acc[nt][2] * acc[nt][2] + acc[nt][3] * acc[nt][3];
    }
#pragma unroll
    for (int h = 0; h < 2; h++) {
        s[h] += __shfl_xor_sync(0xffffffffu, s[h], 1);
        q[h] += __shfl_xor_sync(0xffffffffu, q[h], 1);
        s[h] += __shfl_xor_sync(0xffffffffu, s[h], 2);
        q[h] += __shfl_xor_sync(0xffffffffu, q[h], 2);
    }
    if (t4 == 0) {
#pragma unroll
        for (int h = 0; h < 2; h++) {
            const int row = mw * 16 + h * 8 + g;
            ps[row * 4 + nw] = s[h];
            pq[row * 4 + nw] = q[h];
        }
    }
    __syncthreads();
    if (tid < 64) {
        float ss = ps[tid * 4 + 0] + ps[tid * 4 + 1]
                 + ps[tid * 4 + 2] + ps[tid * 4 + 3];
        float qq = pq[tid * 4 + 0] + pq[tid * 4 + 1]
                 + pq[tid * 4 + 2] + pq[tid * 4 + 3];
        const float mu  = ss * (1.0f / 512.0f);
        const float var = qq * (1.0f / 512.0f) - mu * mu;
        mz[tid] = make_float2(mu, rsqrtf(var + 1e-5f));
    }
    __syncthreads();

#pragma unroll
    for (int h = 0; h < 2; h++) {
        const int row = mw * 16 + h * 8 + g;
        const float2 m = mz[row];
#pragma unroll
        for (int nt = 0; nt < 16; nt++) {
            const int col = nw * 128 + nt * 8 + t4 * 2;
            const float2 gv = *(const float2*)(gamma + col);
            const float2 tv = *(const float2*)(beta + col);
            const float v0 = acc[nt][h * 2 + 0];
            const float v1 = acc[nt][h * 2 + 1];
            const float o0 = fmaxf((v0 - m.x) * m.y * gv.x + tv.x, 0.0f);
            const float o1 = fmaxf((v1 - m.x) * m.y * gv.y + tv.y, 0.0f);
            *(float2*)(out + (size_t)(m0 + row) * 512 + col) = make_float2(o0, o1);
        }
    }
}

extern "C" void kernel_launch(void* const* d_in, const int* in_sizes, int n_in,
                              void* d_out, int out_size)
{
    // metadata order: embeddings, W_proj, b_proj, W_enc, b_enc, ln_gamma, ln_beta
    const float* emb   = (const float*)d_in[0];
    const float* W_enc = (const float*)d_in[3];
    const float* b_enc = (const float*)d_in[4];
    const float* gam   = (const float*)d_in[5];
    const float* bet   = (const float*)d_in[6];
    float* out = (float*)d_out;

    prep_b_kernel<<<128, 256>>>(W_enc);

    cudaFuncSetAttribute(gemm_ln_kernel,
                         cudaFuncAttributeMaxDynamicSharedMemorySize, SMEM_TOTAL);
    gemm_ln_kernel<<<16384 / MTILE, THREADS, SMEM_TOTAL>>>(emb, b_enc, gam, bet, out);
}

// round 8
// speedup vs baseline: 1.1650x; 1.1650x over previous
#include <cuda_runtime.h>
#include <cuda_bf16.h>
#include <cstdint>

// ============================================================================
// SimplifiedTopologyExtractor — algebraic reduction:
//   out = ReLU(LayerNorm(emb[:, :, :256] @ W_enc + b_enc))
// (pooled == embeddings exactly; proj/cdist/topk is dead code.)
//
// fp32 GEMM via bf16 hi/lo split on mma.sync m16n8k16:
//   a*b ≈ ah*bh + ah*bl + al*bh   (err ~2^-18 rel).
// Round 8: R3-R7 were bound by per-16B cp.async ISSUE cost (2048 ops/chunk
// x 8cyc/SMSP ~= the entire 56us wall). Replace with ONE cp.async.bulk
// (UBLKCP, sm_90 base feature) per 32KB B chunk + mbarrier expect_tx.
// B rows become 1024B linear with XOR-unit swizzle for conflict-free LDSM.
// ============================================================================

#define THREADS 512
#define MTILE 64
#define KD 256
#define KCH 16
#define NCHUNK (KD / KCH)
#define STAGES 3

#define B_CHUNK 32768          // hi 16KB + lo 16KB, linear, swizzled
#define A_STRIDE 48
#define OFF_A_H 0              // 64*48 = 3072
#define OFF_A_L 3072
#define OFF_B   6144
#define STAGE_SZ (OFF_B + B_CHUNK)      // 38912
#define OFF_MBAR (STAGES * STAGE_SZ)    // 116736 (3 x 8B)
#define OFF_PS  (OFF_MBAR + 64)
#define OFF_PQ  (OFF_PS + 1024)
#define OFF_MZ  (OFF_PQ + 1024)
#define SMEM_TOTAL (OFF_MZ + 512)       // 119360

// prepped B (bf16 hi/lo), chunk-shaped + swizzled:
//   [chunk 16][part 2][kr 16][unit 64]  where unit' = unit ^ (kr&7)
__device__ __align__(128) unsigned char g_Bpre[16 * B_CHUNK];   // 512 KB

__device__ __forceinline__ uint32_t smem_u32(const void* p) {
    uint32_t a;
    asm("{ .reg .u64 t; cvta.to.shared.u64 t, %1; cvt.u32.u64 %0, t; }"
        : "=r"(a) : "l"(p));
    return a;
}

__device__ __forceinline__ void ldsm4(uint32_t* r, uint32_t addr) {
    asm volatile("ldmatrix.sync.aligned.m8n8.x4.shared.b16 {%0,%1,%2,%3}, [%4];"
                 : "=r"(r[0]), "=r"(r[1]), "=r"(r[2]), "=r"(r[3]) : "r"(addr));
}
__device__ __forceinline__ void ldsm4t(uint32_t* r, uint32_t addr) {
    asm volatile("ldmatrix.sync.aligned.m8n8.x4.trans.shared.b16 {%0,%1,%2,%3}, [%4];"
                 : "=r"(r[0]), "=r"(r[1]), "=r"(r[2]), "=r"(r[3]) : "r"(addr));
}

__device__ __forceinline__ void mma16816(float* d, const uint32_t* a,
                                         uint32_t b0, uint32_t b1) {
    asm volatile(
        "mma.sync.aligned.m16n8k16.row.col.f32.bf16.bf16.f32 "
        "{%0,%1,%2,%3}, {%4,%5,%6,%7}, {%8,%9}, {%0,%1,%2,%3};"
        : "+f"(d[0]), "+f"(d[1]), "+f"(d[2]), "+f"(d[3])
        : "r"(a[0]), "r"(a[1]), "r"(a[2]), "r"(a[3]), "r"(b0), "r"(b1));
}

#define MBAR_INIT(addr, cnt) \
    asm volatile("mbarrier.init.shared.b64 [%0], %1;" :: "r"(addr), "r"(cnt) : "memory")

#define MBAR_EXPECT_TX(addr, bytes) \
    asm volatile("mbarrier.arrive.expect_tx.shared.b64 _, [%0], %1;" \
                 :: "r"(addr), "r"((uint32_t)(bytes)) : "memory")

#define MBAR_WAIT(addr, par) do {                                              \
    uint32_t _m = (addr), _p = (uint32_t)(par), _done;                         \
    asm volatile("{\n\t.reg .pred p;\n\t"                                      \
        "mbarrier.try_wait.parity.acquire.cta.shared::cta.b64 p, [%1], %2;\n\t"\
        "selp.b32 %0, 1, 0, p;\n\t}" : "=r"(_done) : "r"(_m), "r"(_p) : "memory"); \
    if (!_done) {                                                              \
        asm volatile("{\n\t.reg .pred P1;\n\t"                                 \
            "W%=:\n\t"                                                         \
            "mbarrier.try_wait.parity.acquire.cta.shared::cta.b64 P1, [%0], %1, 0x989680;\n\t" \
            "@P1 bra.uni D%=;\n\t"                                             \
            "bra.uni W%=;\n\t"                                                 \
            "D%=:\n\t}" :: "r"(_m), "r"(_p) : "memory");                       \
    }                                                                          \
} while (0)

__device__ __forceinline__ void bulk_copy(uint32_t dst, const void* src,
                                          uint32_t bytes, uint32_t mbar) {
    asm volatile(
        "cp.async.bulk.shared::cluster.global.mbarrier::complete_tx::bytes "
        "[%0], [%1], %2, [%3];"
        :: "r"(dst), "l"(src), "r"(bytes), "r"(mbar) : "memory");
}

// ---- prep B: W_enc[256,512] -> hi/lo bf16, chunk-tiled + XOR swizzle ----
__global__ void prep_b_kernel(const float* __restrict__ W) {
    int t = blockIdx.x * 256 + threadIdx.x;   // 256 k x 128 nq
    int k  = t >> 7;
    int nq = t & 127;
    float4 v = *(const float4*)(W + (size_t)k * 512 + nq * 4);
    float f[4] = {v.x, v.y, v.z, v.w};
    unsigned short hs[4], ls[4];
#pragma unroll
    for (int i = 0; i < 4; i++) {
        __nv_bfloat16 h = __float2bfloat16(f[i]);
        float rem = f[i] - __bfloat162float(h);
        __nv_bfloat16 l = __float2bfloat16(rem);
        hs[i] = __bfloat16_as_ushort(h);
        ls[i] = __bfloat16_as_ushort(l);
    }
    uint2 hp = make_uint2((uint32_t)hs[0] | ((uint32_t)hs[1] << 16),
                          (uint32_t)hs[2] | ((uint32_t)hs[3] << 16));
    uint2 lp = make_uint2((uint32_t)ls[0] | ((uint32_t)ls[1] << 16),
                          (uint32_t)ls[2] | ((uint32_t)ls[3] << 16));
    int c = k >> 4, kr = k & 15;
    int unit = nq >> 1;                       // 16B unit within 1024B row
    int sw   = unit ^ (kr & 7);
    size_t base = (size_t)c * B_CHUNK + (size_t)kr * 1024
                + (size_t)sw * 16 + (nq & 1) * 8;
    *(uint2*)(g_Bpre + base)         = hp;    // hi part
    *(uint2*)(g_Bpre + base + 16384) = lp;    // lo part
}

// ---- GEMM + fused bias/LayerNorm/ReLU ----
__global__ void __launch_bounds__(THREADS, 1)
gemm_ln_kernel(const float* __restrict__ emb,
               const float* __restrict__ bias,
               const float* __restrict__ gamma,
               const float* __restrict__ beta,
               float* __restrict__ out)
{
    extern __shared__ __align__(1024) unsigned char smem[];
    const uint32_t sb = smem_u32(smem);
    const int tid = threadIdx.x;
    const int wid = tid >> 5;
    const int lane = tid & 31;
    const int mw = wid >> 2;       // 4 m-warps (rows mw*16..+16)
    const int nw = wid & 3;        // 4 n-warps (cols nw*128..+128)
    const int m0 = blockIdx.x * MTILE;

    float acc[16][4];
#pragma unroll
    for (int nt = 0; nt < 16; nt++)
#pragma unroll
        for (int e = 0; e < 4; e++) acc[nt][e] = 0.0f;

    // mbarriers
    if (tid == 0) {
        MBAR_INIT(sb + OFF_MBAR + 0, 1);
        MBAR_INIT(sb + OFF_MBAR + 8, 1);
        MBAR_INIT(sb + OFF_MBAR + 16, 1);
    }
    __syncthreads();

    // A staging: thread owns one float2 of the 64x16 chunk
    const int a_row = tid >> 3, a_kp = tid & 7;
    const float* a_src = emb + (size_t)(m0 + a_row) * 512 + a_kp * 2;
    const uint32_t a_off = (uint32_t)a_row * A_STRIDE + (uint32_t)a_kp * 4;

#define STS_A(stg, v) do {                                                      \
    const uint32_t _so = (uint32_t)(stg) * STAGE_SZ;                            \
    __nv_bfloat16 _h0 = __float2bfloat16((v).x);                                \
    __nv_bfloat16 _h1 = __float2bfloat16((v).y);                                \
    __nv_bfloat16 _l0 = __float2bfloat16((v).x - __bfloat162float(_h0));        \
    __nv_bfloat16 _l1 = __float2bfloat16((v).y - __bfloat162float(_h1));        \
    uint32_t _h01 = (uint32_t)__bfloat16_as_ushort(_h0)                         \
                  | ((uint32_t)__bfloat16_as_ushort(_h1) << 16);                \
    uint32_t _l01 = (uint32_t)__bfloat16_as_ushort(_l0)                         \
                  | ((uint32_t)__bfloat16_as_ushort(_l1) << 16);                \
    *(uint32_t*)(smem + _so + OFF_A_H + a_off) = _h01;                          \
    *(uint32_t*)(smem + _so + OFF_A_L + a_off) = _l01;                          \
} while (0)

#define ISSUE_B(cc) do {                                                        \
    const int _c = (cc);                                                        \
    const int _s = _c % STAGES;                                                 \
    const uint32_t _mb = sb + OFF_MBAR + _s * 8;                                \
    MBAR_EXPECT_TX(_mb, B_CHUNK);                                               \
    bulk_copy(sb + (uint32_t)_s * STAGE_SZ + OFF_B,                             \
              g_Bpre + (size_t)_c * B_CHUNK, B_CHUNK, _mb);                     \
} while (0)

    // ---- prologue ----
    {
        float2 a0 = *(const float2*)(a_src);
        float2 a1 = *(const float2*)(a_src + 16);
        STS_A(0, a0);
        STS_A(1, a1);
    }
    if (tid == 0) {
        ISSUE_B(0);
        ISSUE_B(1);
    }
    float2 aR = *(const float2*)(a_src + 32);

    // ldmatrix lane addressing
    const uint32_t lrow = lane & 15, lchk = lane >> 4;
    const uint32_t aLane = lrow * A_STRIDE + lchk * 16
                         + (uint32_t)mw * 16 * A_STRIDE;
    const uint32_t bRow = lrow * 1024;         // 1024B rows in bulk layout
    const uint32_t swz  = lrow & 7;            // XOR-unit de-swizzle
    const uint32_t uBase = (uint32_t)nw * 16 + lchk;

    int s = 0, p = 0;                          // stage cursor + parity
#pragma unroll 1
    for (int c = 0; c < NCHUNK; ++c) {
        MBAR_WAIT(sb + OFF_MBAR + s * 8, p);   // B(c) landed
        __syncthreads();                        // A(c) visible; stage s2 free

        if (c + 2 < NCHUNK) {
            int s2 = s + 2; if (s2 >= STAGES) s2 -= STAGES;
            STS_A(s2, aR);
            if (tid == 0) ISSUE_B(c + 2);
        }
        if (c + 3 < NCHUNK) aR = *(const float2*)(a_src + (c + 3) * 16);

        const uint32_t st = sb + (uint32_t)s * STAGE_SZ;
        uint32_t Ah[4], Al[4];
        ldsm4(Ah, st + OFF_A_H + aLane);
        ldsm4(Al, st + OFF_A_L + aLane);
        const uint32_t bH = st + OFF_B + bRow;
#pragma unroll
        for (int j = 0; j < 8; j++) {
            const uint32_t u = uBase + (uint32_t)j * 2;
            const uint32_t addrH = bH + ((u ^ swz) << 4);
            uint32_t Bh[4], Bl[4];
            ldsm4t(Bh, addrH);
            ldsm4t(Bl, addrH + 16384);
#pragma unroll
            for (int nn = 0; nn < 2; nn++) {
                float* d = acc[j * 2 + nn];
                mma16816(d, Ah, Bh[nn * 2], Bh[nn * 2 + 1]);
                mma16816(d, Ah, Bl[nn * 2], Bl[nn * 2 + 1]);
                mma16816(d, Al, Bh[nn * 2], Bh[nn * 2 + 1]);
            }
        }
        if (++s == STAGES) { s = 0; p ^= 1; }
    }

    // ======== fused epilogue: +bias, LayerNorm(512), *gamma+beta, ReLU ========
    const int g = lane >> 2, t4 = lane & 3;
    float* ps = (float*)(smem + OFF_PS);      // [64 rows][4 nw]
    float* pq = (float*)(smem + OFF_PQ);
    float2* mz = (float2*)(smem + OFF_MZ);    // [64] {mu, rstd}

    float sA[2] = {0.f, 0.f}, qA[2] = {0.f, 0.f};
#pragma unroll
    for (int nt = 0; nt < 16; nt++) {
        const int col = nw * 128 + nt * 8 + t4 * 2;
        const float2 bv = *(const float2*)(bias + col);
        acc[nt][0] += bv.x; acc[nt][1] += bv.y;
        acc[nt][2] += bv.x; acc[nt][3] += bv.y;
        sA[0] += acc[nt][0] + acc[nt][1];
        qA[0] += acc[nt][0] * acc[nt][0] + acc[nt][1] * acc[nt][1];
        sA[1] += acc[nt][2] + acc[nt][3];
        qA[1] += acc[nt][2] * acc[nt][2] + acc[nt][3] * acc[nt][3];
    }
#pragma unroll
    for (int h = 0; h < 2; h++) {
        sA[h] += __shfl_xor_sync(0xffffffffu, sA[h], 1);
        qA[h] += __shfl_xor_sync(0xffffffffu, qA[h], 1);
        sA[h] += __shfl_xor_sync(0xffffffffu, sA[h], 2);
        qA[h] += __shfl_xor_sync(0xffffffffu, qA[h], 2);
    }
    if (t4 == 0) {
#pragma unroll
        for (int h = 0; h < 2; h++) {
            const int row = mw * 16 + h * 8 + g;
            ps[row * 4 + nw] = sA[h];
            pq[row * 4 + nw] = qA[h];
        }
    }
    __syncthreads();
    if (tid < 64) {
        float ss = ps[tid * 4 + 0] + ps[tid * 4 + 1]
                 + ps[tid * 4 + 2] + ps[tid * 4 + 3];
        float qq = pq[tid * 4 + 0] + pq[tid * 4 + 1]
                 + pq[tid * 4 + 2] + pq[tid * 4 + 3];
        const float mu  = ss * (1.0f / 512.0f);
        const float var = qq * (1.0f / 512.0f) - mu * mu;
        mz[tid] = make_float2(mu, rsqrtf(var + 1e-5f));
    }
    __syncthreads();

#pragma unroll
    for (int h = 0; h < 2; h++) {
        const int row = mw * 16 + h * 8 + g;
        const float2 m = mz[row];
#pragma unroll
        for (int nt = 0; nt < 16; nt++) {
            const int col = nw * 128 + nt * 8 + t4 * 2;
            const float2 gv = *(const float2*)(gamma + col);
            const float2 tv = *(const float2*)(beta + col);
            const float v0 = acc[nt][h * 2 + 0];
            const float v1 = acc[nt][h * 2 + 1];
            const float o0 = fmaxf((v0 - m.x) * m.y * gv.x + tv.x, 0.0f);
            const float o1 = fmaxf((v1 - m.x) * m.y * gv.y + tv.y, 0.0f);
            *(float2*)(out + (size_t)(m0 + row) * 512 + col) = make_float2(o0, o1);
        }
    }
}

extern "C" void kernel_launch(void* const* d_in, const int* in_sizes, int n_in,
                              void* d_out, int out_size)
{
    // metadata order: embeddings, W_proj, b_proj, W_enc, b_enc, ln_gamma, ln_beta
    const float* emb   = (const float*)d_in[0];
    const float* W_enc = (const float*)d_in[3];
    const float* b_enc = (const float*)d_in[4];
    const float* gam   = (const float*)d_in[5];
    const float* bet   = (const float*)d_in[6];
    float* out = (float*)d_out;

    prep_b_kernel<<<128, 256>>>(W_enc);

    cudaFuncSetAttribute(gemm_ln_kernel,
                         cudaFuncAttributeMaxDynamicSharedMemorySize, SMEM_TOTAL);
    gemm_ln_kernel<<<16384 / MTILE, THREADS, SMEM_TOTAL>>>(emb, b_enc, gam, bet, out);
}